// round 5
// baseline (speedup 1.0000x reference)
#include <cuda_runtime.h>
#include <math.h>

// Problem constants
#define BN   2
#define CIN  64
#define HH   80
#define WW   80
#define HWSZ 6400
#define COUT 64

// ---------------- scratch (device globals; no allocation allowed) ----------------
__device__ float g_xn[BN * HWSZ * CIN];          // x transposed to NHWC

__device__ float g_Wc3[9  * CIN * 27];           // conv weights reordered [t][c][n]
__device__ float g_Wc5[25 * CIN * 75];
__device__ float g_Wc7[49 * CIN * 147];
__device__ float g_Wd3[9  * CIN * COUT];         // dcn weights reordered [t][c][o]
__device__ float g_Wd5[25 * CIN * COUT];
__device__ float g_Wd7[49 * CIN * COUT];
__device__ float g_bc3[27];                      // combined bias [off..., mask...]
__device__ float g_bc5[75];
__device__ float g_bc7[147];
__device__ float g_om3[BN * 27  * HWSZ];         // conv output [b][n][p] (mask already sigmoided)
__device__ float g_om5[BN * 75  * HWSZ];
__device__ float g_om7[BN * 147 * HWSZ];

template<int K> __device__ __forceinline__ float* WcP() {
    if constexpr (K == 3) return g_Wc3; else if constexpr (K == 5) return g_Wc5; else return g_Wc7;
}
template<int K> __device__ __forceinline__ float* WdP() {
    if constexpr (K == 3) return g_Wd3; else if constexpr (K == 5) return g_Wd5; else return g_Wd7;
}
template<int K> __device__ __forceinline__ float* bcP() {
    if constexpr (K == 3) return g_bc3; else if constexpr (K == 5) return g_bc5; else return g_bc7;
}
template<int K> __device__ __forceinline__ float* omP() {
    if constexpr (K == 3) return g_om3; else if constexpr (K == 5) return g_om5; else return g_om7;
}

// ---------------- NCHW -> NHWC transpose ----------------
__global__ void k_transpose(const float* __restrict__ x) {
    int id = blockIdx.x * 256 + threadIdx.x;
    if (id >= BN * HWSZ * CIN) return;
    int c    = id & 63;
    int rest = id >> 6;
    int p    = rest % HWSZ;
    int b    = rest / HWSZ;
    g_xn[id] = x[(b * CIN + c) * HWSZ + p];
}

// ---------------- weight reorders ----------------
// Wc[t][c][n]: n<2kk -> w_off[n][c][t], else w_mask[n-2kk][c][t].  bc combined bias.
template<int K>
__global__ void k_reorder_conv(const float* __restrict__ w_off, const float* __restrict__ b_off,
                               const float* __restrict__ w_mask, const float* __restrict__ b_mask) {
    constexpr int KK = K * K, NC = 3 * KK;
    int id = blockIdx.x * 256 + threadIdx.x;
    int total = KK * CIN * NC;
    if (id < total) {
        int n = id % NC;
        int c = (id / NC) % CIN;
        int t = id / (NC * CIN);
        float v = (n < 2 * KK) ? w_off[(n * CIN + c) * KK + t]
                               : w_mask[((n - 2 * KK) * CIN + c) * KK + t];
        WcP<K>()[id] = v;
    }
    if (id < NC)
        bcP<K>()[id] = (id < 2 * KK) ? b_off[id] : b_mask[id - 2 * KK];
}

// Wd[t][c][o] = w_dcn[o][c][t]
template<int K>
__global__ void k_reorder_dcn(const float* __restrict__ w_dcn) {
    constexpr int KK = K * K;
    int id = blockIdx.x * 256 + threadIdx.x;
    if (id >= KK * CIN * COUT) return;
    int o = id % COUT;
    int c = (id / COUT) % CIN;
    int t = id / (COUT * CIN);
    WdP<K>()[id] = w_dcn[(o * CIN + c) * KK + t];
}

// ---------------- fused offset+mask conv (implicit GEMM, K streamed per tap) ----------------
// Block: 64 pixels x 64 out-channels, 256 threads, 4x4 register tile.
template<int K>
__global__ __launch_bounds__(256) void k_conv() {
    constexpr int KK = K * K, NC = 3 * KK, PAD = K / 2;
    __shared__ float As[64][64];   // As[p][c] patch values
    __shared__ float Bs[64][64];   // Bs[c][n] weights
    const int p0  = blockIdx.x * 64;
    const int n0  = blockIdx.y * 64;
    const int b   = blockIdx.z;
    const int tid = threadIdx.x;
    const int tx  = tid & 15, ty = tid >> 4;
    const float* __restrict__ xb = g_xn + b * HWSZ * CIN;
    const float* __restrict__ Wc = WcP<K>();
    float acc[4][4] = {};

    for (int t = 0; t < KK; ++t) {
        const int iy = t / K, ix = t % K;
        __syncthreads();                       // protect smem vs previous GEMM reads
        #pragma unroll
        for (int r = 0; r < 4; ++r) {          // load A tile (64px x 64c)
            int task = tid + r * 256;
            int p = task >> 4, c4 = (task & 15) << 2;
            int pg = p0 + p;
            int yy = pg / WW - PAD + iy;
            int xx = pg % WW - PAD + ix;
            float4 v = make_float4(0.f, 0.f, 0.f, 0.f);
            if (yy >= 0 && yy < HH && xx >= 0 && xx < WW)
                v = *reinterpret_cast<const float4*>(xb + (yy * WW + xx) * CIN + c4);
            *reinterpret_cast<float4*>(&As[p][c4]) = v;
        }
        #pragma unroll
        for (int r = 0; r < 4; ++r) {          // load B tile (64c x 64n, zero-fill past NC)
            int task = tid + r * 256;
            int c = task >> 4, n4 = (task & 15) << 2;
            const float* wrow = Wc + (t * CIN + c) * NC + n0 + n4;
            int nrem = NC - (n0 + n4);
            float4 v;
            v.x = (0 < nrem) ? wrow[0] : 0.f;
            v.y = (1 < nrem) ? wrow[1] : 0.f;
            v.z = (2 < nrem) ? wrow[2] : 0.f;
            v.w = (3 < nrem) ? wrow[3] : 0.f;
            *reinterpret_cast<float4*>(&Bs[c][n4]) = v;
        }
        __syncthreads();
        #pragma unroll 16
        for (int c = 0; c < 64; ++c) {
            float4 b4 = *reinterpret_cast<const float4*>(&Bs[c][tx << 2]);
            #pragma unroll
            for (int i = 0; i < 4; ++i) {
                float a = As[(ty << 2) + i][c];
                acc[i][0] += a * b4.x; acc[i][1] += a * b4.y;
                acc[i][2] += a * b4.z; acc[i][3] += a * b4.w;
            }
        }
    }

    const float* __restrict__ bc = bcP<K>();
    float* __restrict__ om = omP<K>();
    #pragma unroll
    for (int j = 0; j < 4; ++j) {
        int n = n0 + (tx << 2) + j;
        if (n >= NC) continue;
        float bias = bc[n];
        #pragma unroll
        for (int i = 0; i < 4; ++i) {
            float v = acc[i][j] + bias;
            if (n >= 2 * KK) v = 1.f / (1.f + expf(-v));   // sigmoid fused for mask channels
            om[(b * NC + n) * HWSZ + p0 + (ty << 2) + i] = v;
        }
    }
}

// ---------------- fused bilinear sampling + deform GEMM ----------------
// Block: 32 pixels x 64 out-channels; per tap: corner precompute -> gather into smem -> GEMM.
template<int K>
__global__ __launch_bounds__(256) void k_deform(float* __restrict__ out) {
    constexpr int KK = K * K, NC = 3 * KK, PAD = K / 2;
    constexpr int OB = (K == 3) ? 0 : (K == 5) ? 64 : 128;   // output channel base (concat)
    __shared__ float Ss[32][64];       // sampled tile [p][c] (mask folded in)
    __shared__ float Ws[64][64];       // weight slice [c][o] for this tap
    __shared__ int   sIdx[4][32];
    __shared__ float sW[4][32];
    const int p0  = blockIdx.x * 32;
    const int b   = blockIdx.y;
    const int tid = threadIdx.x;
    const int tx  = tid & 15, ty = tid >> 4;
    const float* __restrict__ xb  = g_xn + b * HWSZ * CIN;
    const float* __restrict__ omb = omP<K>() + b * NC * HWSZ;
    const float* __restrict__ Wd  = WdP<K>();
    float acc[2][4] = {};

    for (int t = 0; t < KK; ++t) {
        __syncthreads();
        #pragma unroll
        for (int r = 0; r < 4; ++r) {                          // 16KB weight slice, coalesced
            int slot = tid + r * 256;
            reinterpret_cast<float4*>(&Ws[0][0])[slot] =
                reinterpret_cast<const float4*>(Wd + t * (CIN * COUT))[slot];
        }
        if (tid < 32) {                                        // corner indices + weights
            int p = tid, pg = p0 + p;
            float oy = omb[(2 * t)     * HWSZ + pg];
            float ox = omb[(2 * t + 1) * HWSZ + pg];
            float m  = omb[(2 * KK + t) * HWSZ + pg];
            float py = (float)(pg / WW - PAD + t / K) + oy;
            float px = (float)(pg % WW - PAD + t % K) + ox;
            float y0f = floorf(py), x0f = floorf(px);
            float wy1 = py - y0f, wx1 = px - x0f;
            float wy0 = 1.f - wy1, wx0 = 1.f - wx1;
            #pragma unroll
            for (int j = 0; j < 4; ++j) {
                float yf = y0f + (float)(j >> 1);
                float xf = x0f + (float)(j & 1);
                bool valid = (yf >= 0.f) && (yf <= (float)(HH - 1)) &&
                             (xf >= 0.f) && (xf <= (float)(WW - 1));
                int yc = (int)fminf(fmaxf(yf, 0.f), (float)(HH - 1));
                int xc = (int)fminf(fmaxf(xf, 0.f), (float)(WW - 1));
                float wgt = ((j >> 1) ? wy1 : wy0) * ((j & 1) ? wx1 : wx0) * m;
                sIdx[j][p] = yc * WW + xc;
                sW[j][p]   = valid ? wgt : 0.f;
            }
        }
        __syncthreads();
        #pragma unroll
        for (int r = 0; r < 2; ++r) {                          // gather 32px x 64c tile
            int task = tid + r * 256;
            int p = task >> 4, c4 = (task & 15) << 2;
            float4 a = make_float4(0.f, 0.f, 0.f, 0.f);
            #pragma unroll
            for (int j = 0; j < 4; ++j) {
                float wgt = sW[j][p];
                const float4 v = *reinterpret_cast<const float4*>(xb + sIdx[j][p] * CIN + c4);
                a.x += wgt * v.x; a.y += wgt * v.y; a.z += wgt * v.z; a.w += wgt * v.w;
            }
            *reinterpret_cast<float4*>(&Ss[p][c4]) = a;
        }
        __syncthreads();
        #pragma unroll 16
        for (int c = 0; c < 64; ++c) {
            float4 b4 = *reinterpret_cast<const float4*>(&Ws[c][tx << 2]);
            #pragma unroll
            for (int i = 0; i < 2; ++i) {
                float a = Ss[(ty << 1) + i][c];
                acc[i][0] += a * b4.x; acc[i][1] += a * b4.y;
                acc[i][2] += a * b4.z; acc[i][3] += a * b4.w;
            }
        }
    }

    #pragma unroll
    for (int j = 0; j < 4; ++j) {
        int o = OB + (tx << 2) + j;
        #pragma unroll
        for (int i = 0; i < 2; ++i)
            out[(b * 192 + o) * HWSZ + p0 + (ty << 1) + i] = acc[i][j];
    }
}

// ---------------- launch ----------------
extern "C" void kernel_launch(void* const* d_in, const int* in_sizes, int n_in,
                              void* d_out, int out_size) {
    (void)in_sizes; (void)n_in; (void)out_size;
    const float* x       = (const float*)d_in[0];
    const float* w_off3  = (const float*)d_in[1];
    const float* b_off3  = (const float*)d_in[2];
    const float* w_mask3 = (const float*)d_in[3];
    const float* b_mask3 = (const float*)d_in[4];
    const float* w_dcn3  = (const float*)d_in[5];
    const float* w_off5  = (const float*)d_in[6];
    const float* b_off5  = (const float*)d_in[7];
    const float* w_mask5 = (const float*)d_in[8];
    const float* b_mask5 = (const float*)d_in[9];
    const float* w_dcn5  = (const float*)d_in[10];
    const float* w_off7  = (const float*)d_in[11];
    const float* b_off7  = (const float*)d_in[12];
    const float* w_mask7 = (const float*)d_in[13];
    const float* b_mask7 = (const float*)d_in[14];
    const float* w_dcn7  = (const float*)d_in[15];
    float* out = (float*)d_out;

    k_transpose<<<(BN * HWSZ * CIN + 255) / 256, 256>>>(x);

    k_reorder_conv<3><<<(9  * CIN * 27  + 255) / 256, 256>>>(w_off3, b_off3, w_mask3, b_mask3);
    k_reorder_conv<5><<<(25 * CIN * 75  + 255) / 256, 256>>>(w_off5, b_off5, w_mask5, b_mask5);
    k_reorder_conv<7><<<(49 * CIN * 147 + 255) / 256, 256>>>(w_off7, b_off7, w_mask7, b_mask7);
    k_reorder_dcn<3><<<(9  * CIN * COUT + 255) / 256, 256>>>(w_dcn3);
    k_reorder_dcn<5><<<(25 * CIN * COUT + 255) / 256, 256>>>(w_dcn5);
    k_reorder_dcn<7><<<(49 * CIN * COUT + 255) / 256, 256>>>(w_dcn7);

    k_conv<3><<<dim3(HWSZ / 64, 1, BN), 256>>>();
    k_conv<5><<<dim3(HWSZ / 64, 2, BN), 256>>>();
    k_conv<7><<<dim3(HWSZ / 64, 3, BN), 256>>>();

    k_deform<3><<<dim3(HWSZ / 32, BN), 256>>>(out);
    k_deform<5><<<dim3(HWSZ / 32, BN), 256>>>(out);
    k_deform<7><<<dim3(HWSZ / 32, BN), 256>>>(out);
}

// round 7
// speedup vs baseline: 2.1333x; 2.1333x over previous
#include <cuda_runtime.h>
#include <math.h>

// Problem constants
#define BN   2
#define CIN  64
#define HH   80
#define WW   80
#define HWSZ 6400
#define COUT 64
#define SST  36              // smem k-stride: 32 data + 4 pad  (36 % 32 == 4 -> conflict-free frags)

// ---------------- scratch (device globals; no allocation allowed) ----------------
__device__ float g_xn[BN * HWSZ * CIN];          // x in NHWC

__device__ float g_Wc3[9  * 27  * CIN];          // conv weights [t][n][c]
__device__ float g_Wc5[25 * 75  * CIN];
__device__ float g_Wc7[49 * 147 * CIN];
__device__ float g_Wd3[9  * COUT * CIN];         // dcn weights [t][o][c]
__device__ float g_Wd5[25 * COUT * CIN];
__device__ float g_Wd7[49 * COUT * CIN];
__device__ float g_bc3[27], g_bc5[75], g_bc7[147];
__device__ float g_om3[BN * 27  * HWSZ];         // conv out [b][n][p] (mask sigmoided)
__device__ float g_om5[BN * 75  * HWSZ];
__device__ float g_om7[BN * 147 * HWSZ];

template<int K> __device__ __forceinline__ float* WcP() {
    if constexpr (K == 3) return g_Wc3; else if constexpr (K == 5) return g_Wc5; else return g_Wc7;
}
template<int K> __device__ __forceinline__ float* WdP() {
    if constexpr (K == 3) return g_Wd3; else if constexpr (K == 5) return g_Wd5; else return g_Wd7;
}
template<int K> __device__ __forceinline__ float* bcP() {
    if constexpr (K == 3) return g_bc3; else if constexpr (K == 5) return g_bc5; else return g_bc7;
}
template<int K> __device__ __forceinline__ float* omP() {
    if constexpr (K == 3) return g_om3; else if constexpr (K == 5) return g_om5; else return g_om7;
}

// ---------------- tf32 helpers ----------------
__device__ __forceinline__ unsigned f2tf(float f) {
    unsigned u; asm("cvt.rna.tf32.f32 %0, %1;" : "=r"(u) : "f"(f)); return u;
}
__device__ __forceinline__ void mma_tf32(float* c, const unsigned* a, const unsigned* b) {
    asm volatile(
        "mma.sync.aligned.m16n8k8.row.col.f32.tf32.tf32.f32 "
        "{%0,%1,%2,%3},{%4,%5,%6,%7},{%8,%9},{%0,%1,%2,%3};"
        : "+f"(c[0]), "+f"(c[1]), "+f"(c[2]), "+f"(c[3])
        : "r"(a[0]), "r"(a[1]), "r"(a[2]), "r"(a[3]), "r"(b[0]), "r"(b[1]));
}

// ---------------- NCHW -> NHWC transpose ----------------
__global__ void k_transpose(const float* __restrict__ x) {
    int id = blockIdx.x * 256 + threadIdx.x;
    if (id >= BN * HWSZ * CIN) return;
    int c    = id & 63;
    int rest = id >> 6;
    int p    = rest % HWSZ;
    int b    = rest / HWSZ;
    g_xn[id] = x[(b * CIN + c) * HWSZ + p];
}

// ---------------- weight reorders ----------------
// Wc[t][n][c]: n<2kk -> w_off[n][c][t], else w_mask[n-2kk][c][t].  bc = combined bias.
template<int K>
__global__ void k_reorder_conv(const float* __restrict__ w_off, const float* __restrict__ b_off,
                               const float* __restrict__ w_mask, const float* __restrict__ b_mask) {
    constexpr int KK = K * K, NC = 3 * KK;
    int id = blockIdx.x * 256 + threadIdx.x;
    if (id < KK * NC * CIN) {
        int c = id % CIN;
        int n = (id / CIN) % NC;
        int t = id / (CIN * NC);
        float v = (n < 2 * KK) ? w_off[(n * CIN + c) * KK + t]
                               : w_mask[((n - 2 * KK) * CIN + c) * KK + t];
        WcP<K>()[id] = v;
    }
    if (id < NC)
        bcP<K>()[id] = (id < 2 * KK) ? b_off[id] : b_mask[id - 2 * KK];
}

// Wd[t][o][c] = w_dcn[o][c][t]
template<int K>
__global__ void k_reorder_dcn(const float* __restrict__ w_dcn) {
    constexpr int KK = K * K;
    int id = blockIdx.x * 256 + threadIdx.x;
    if (id >= KK * COUT * CIN) return;
    int c = id % CIN;
    int o = (id / CIN) % COUT;
    int t = id / (CIN * COUT);
    WdP<K>()[id] = w_dcn[(o * CIN + c) * KK + t];
}

// ---------------- fused offset+mask conv: tf32 implicit GEMM ----------------
// Block tile 128px x 64n, 256 thr = 8 warps (4x2), warp tile 32x32, K staged 32/tap-half.
template<int K>
__device__ void conv_body(int mb, int nt, char* smem) {
    constexpr int KK = K * K, NC = 3 * KK, PAD = K / 2;
    unsigned* As = (unsigned*)smem;          // [128][SST]
    unsigned* Bs = As + 128 * SST;           // [64][SST]
    const int tid = threadIdx.x;
    const int w = tid >> 5, lane = tid & 31;
    const int g = lane >> 2, t4 = lane & 3;
    const int wm = (w & 3) * 32, wn = (w >> 2) * 32;
    const int plin = mb * 128;
    const int b = plin / HWSZ, p0 = plin % HWSZ;
    const int n0 = nt * 64;
    const float* __restrict__ xb = g_xn + b * HWSZ * CIN;
    const float* __restrict__ Wc = WcP<K>();
    float acc[2][4][4] = {};

    for (int t = 0; t < KK; ++t) {
        const int iy = t / K - PAD, ix = t % K - PAD;
        for (int h = 0; h < 2; ++h) {
            __syncthreads();
            #pragma unroll
            for (int r = 0; r < 4; ++r) {            // As: 128px x 32c (1024 float4 tasks)
                int task = tid + r * 256;
                int p = task >> 3, c4 = (task & 7) << 2;
                int pg = p0 + p;
                int yy = pg / WW + iy, xx = pg % WW + ix;
                float4 v = make_float4(0.f, 0.f, 0.f, 0.f);
                if (yy >= 0 && yy < HH && xx >= 0 && xx < WW)
                    v = *reinterpret_cast<const float4*>(xb + (yy * WW + xx) * CIN + h * 32 + c4);
                *reinterpret_cast<uint4*>(&As[p * SST + c4]) =
                    make_uint4(f2tf(v.x), f2tf(v.y), f2tf(v.z), f2tf(v.w));
            }
            #pragma unroll
            for (int r = 0; r < 2; ++r) {            // Bs: 64n x 32c (512 float4 tasks)
                int task = tid + r * 256;
                int n = task >> 3, c4 = (task & 7) << 2;
                float4 v = make_float4(0.f, 0.f, 0.f, 0.f);
                if (n0 + n < NC)
                    v = *reinterpret_cast<const float4*>(Wc + (t * NC + n0 + n) * CIN + h * 32 + c4);
                *reinterpret_cast<uint4*>(&Bs[n * SST + c4]) =
                    make_uint4(f2tf(v.x), f2tf(v.y), f2tf(v.z), f2tf(v.w));
            }
            __syncthreads();
            #pragma unroll
            for (int ks = 0; ks < 4; ++ks) {
                const int k0 = ks * 8;
                unsigned a[2][4], bb[4][2];
                #pragma unroll
                for (int mi = 0; mi < 2; ++mi) {
                    int rb = wm + mi * 16;
                    a[mi][0] = As[(rb + g)     * SST + k0 + t4];
                    a[mi][1] = As[(rb + g + 8) * SST + k0 + t4];
                    a[mi][2] = As[(rb + g)     * SST + k0 + t4 + 4];
                    a[mi][3] = As[(rb + g + 8) * SST + k0 + t4 + 4];
                }
                #pragma unroll
                for (int ni = 0; ni < 4; ++ni) {
                    int cb = wn + ni * 8;
                    bb[ni][0] = Bs[(cb + g) * SST + k0 + t4];
                    bb[ni][1] = Bs[(cb + g) * SST + k0 + t4 + 4];
                }
                #pragma unroll
                for (int mi = 0; mi < 2; ++mi)
                    #pragma unroll
                    for (int ni = 0; ni < 4; ++ni)
                        mma_tf32(acc[mi][ni], a[mi], bb[ni]);
            }
        }
    }

    const float* __restrict__ bc = bcP<K>();
    float* __restrict__ om = omP<K>() + b * NC * HWSZ;
    #pragma unroll
    for (int mi = 0; mi < 2; ++mi) {
        int pr0 = p0 + wm + mi * 16 + g;
        #pragma unroll
        for (int ni = 0; ni < 4; ++ni) {
            int n = n0 + wn + ni * 8 + t4 * 2;
            #pragma unroll
            for (int jj = 0; jj < 2; ++jj) {
                int nn = n + jj;
                if (nn >= NC) continue;
                float bias = bc[nn];
                float v0 = acc[mi][ni][jj]     + bias;   // (pr0,   nn)
                float v1 = acc[mi][ni][2 + jj] + bias;   // (pr0+8, nn)
                if (nn >= 2 * KK) {
                    v0 = 1.f / (1.f + expf(-v0));
                    v1 = 1.f / (1.f + expf(-v1));
                }
                om[nn * HWSZ + pr0]     = v0;
                om[nn * HWSZ + pr0 + 8] = v1;
            }
        }
    }
}

__global__ __launch_bounds__(256) void k_conv_all() {
    __shared__ __align__(16) char smem[(128 + 64) * SST * 4];
    int bid = blockIdx.x;
    if (bid < 100)       conv_body<3>(bid, 0, smem);
    else if (bid < 300)  { int r = bid - 100; conv_body<5>(r % 100, r / 100, smem); }
    else                 { int r = bid - 300; conv_body<7>(r % 100, r / 100, smem); }
}

// ---------------- fused bilinear sampling + deform GEMM (tf32) ----------------
// Block tile 64px x 64o, 128 thr = 4 warps (2x2), warp tile 32x32.
template<int K>
__device__ void deform_body(int mb, float* __restrict__ out, char* smem) {
    constexpr int KK = K * K, NC = 3 * KK, PAD = K / 2;
    constexpr int OB = (K == 3) ? 0 : (K == 5) ? 64 : 128;
    unsigned* As  = (unsigned*)smem;                 // [64][SST]
    unsigned* Ws  = As + 64 * SST;                   // [64][SST]
    int*      sIdx = (int*)(Ws + 64 * SST);          // [4][64]
    float*    sW   = (float*)(sIdx + 4 * 64);        // [4][64]
    const int tid = threadIdx.x;
    const int w = tid >> 5, lane = tid & 31;
    const int g = lane >> 2, t4 = lane & 3;
    const int wm = (w & 1) * 32, wn = (w >> 1) * 32;
    const int plin = mb * 64;
    const int b = plin / HWSZ, p0 = plin % HWSZ;
    const float* __restrict__ xb  = g_xn + b * HWSZ * CIN;
    const float* __restrict__ omb = omP<K>() + b * NC * HWSZ;
    const float* __restrict__ Wd  = WdP<K>();
    float acc[2][4][4] = {};

    for (int t = 0; t < KK; ++t) {
        __syncthreads();
        if (tid < 64) {                              // corner idx + weight per pixel
            int p = tid, pg = p0 + p;
            float oy = omb[(2 * t)      * HWSZ + pg];
            float ox = omb[(2 * t + 1)  * HWSZ + pg];
            float m  = omb[(2 * KK + t) * HWSZ + pg];
            float py = (float)(pg / WW - PAD + t / K) + oy;
            float px = (float)(pg % WW - PAD + t % K) + ox;
            float y0f = floorf(py), x0f = floorf(px);
            float wy1 = py - y0f, wx1 = px - x0f;
            float wy0 = 1.f - wy1, wx0 = 1.f - wx1;
            #pragma unroll
            for (int j = 0; j < 4; ++j) {
                float yf = y0f + (float)(j >> 1);
                float xf = x0f + (float)(j & 1);
                bool valid = (yf >= 0.f) && (yf <= (float)(HH - 1)) &&
                             (xf >= 0.f) && (xf <= (float)(WW - 1));
                int yc = (int)fminf(fmaxf(yf, 0.f), (float)(HH - 1));
                int xc = (int)fminf(fmaxf(xf, 0.f), (float)(WW - 1));
                float wgt = ((j >> 1) ? wy1 : wy0) * ((j & 1) ? wx1 : wx0) * m;
                sIdx[j * 64 + p] = yc * WW + xc;
                sW[j * 64 + p]   = valid ? wgt : 0.f;
            }
        }
        __syncthreads();
        for (int h = 0; h < 2; ++h) {
            #pragma unroll
            for (int r = 0; r < 4; ++r) {            // gather As: 64px x 32c
                int task = tid + r * 128;
                int p = task >> 3, c4 = (task & 7) << 2;
                const float* base = xb + h * 32 + c4;
                float4 s = make_float4(0.f, 0.f, 0.f, 0.f);
                #pragma unroll
                for (int j = 0; j < 4; ++j) {
                    float wgt = sW[j * 64 + p];
                    float4 v = *reinterpret_cast<const float4*>(base + sIdx[j * 64 + p] * CIN);
                    s.x += wgt * v.x; s.y += wgt * v.y; s.z += wgt * v.z; s.w += wgt * v.w;
                }
                *reinterpret_cast<uint4*>(&As[p * SST + c4]) =
                    make_uint4(f2tf(s.x), f2tf(s.y), f2tf(s.z), f2tf(s.w));
            }
            #pragma unroll
            for (int r = 0; r < 4; ++r) {            // Ws: 64o x 32c
                int task = tid + r * 128;
                int o = task >> 3, c4 = (task & 7) << 2;
                float4 v = *reinterpret_cast<const float4*>(Wd + (t * COUT + o) * CIN + h * 32 + c4);
                *reinterpret_cast<uint4*>(&Ws[o * SST + c4]) =
                    make_uint4(f2tf(v.x), f2tf(v.y), f2tf(v.z), f2tf(v.w));
            }
            __syncthreads();
            #pragma unroll
            for (int ks = 0; ks < 4; ++ks) {
                const int k0 = ks * 8;
                unsigned a[2][4], bb[4][2];
                #pragma unroll
                for (int mi = 0; mi < 2; ++mi) {
                    int rb = wm + mi * 16;
                    a[mi][0] = As[(rb + g)     * SST + k0 + t4];
                    a[mi][1] = As[(rb + g + 8) * SST + k0 + t4];
                    a[mi][2] = As[(rb + g)     * SST + k0 + t4 + 4];
                    a[mi][3] = As[(rb + g + 8) * SST + k0 + t4 + 4];
                }
                #pragma unroll
                for (int ni = 0; ni < 4; ++ni) {
                    int cb = wn + ni * 8;
                    bb[ni][0] = Ws[(cb + g) * SST + k0 + t4];
                    bb[ni][1] = Ws[(cb + g) * SST + k0 + t4 + 4];
                }
                #pragma unroll
                for (int mi = 0; mi < 2; ++mi)
                    #pragma unroll
                    for (int ni = 0; ni < 4; ++ni)
                        mma_tf32(acc[mi][ni], a[mi], bb[ni]);
            }
            __syncthreads();
        }
    }

    float* __restrict__ ob = out + (size_t)(b * 192 + OB) * HWSZ;
    #pragma unroll
    for (int mi = 0; mi < 2; ++mi) {
        int pr0 = p0 + wm + mi * 16 + g;
        #pragma unroll
        for (int ni = 0; ni < 4; ++ni) {
            int o = wn + ni * 8 + 2 * t4;
            ob[o       * HWSZ + pr0]     = acc[mi][ni][0];
            ob[(o + 1) * HWSZ + pr0]     = acc[mi][ni][1];
            ob[o       * HWSZ + pr0 + 8] = acc[mi][ni][2];
            ob[(o + 1) * HWSZ + pr0 + 8] = acc[mi][ni][3];
        }
    }
}

__global__ __launch_bounds__(128) void k_deform_all(float* __restrict__ out) {
    __shared__ __align__(16) char smem[(64 + 64) * SST * 4 + 4 * 64 * 8];
    int bid = blockIdx.x;
    if (bid < 200)      deform_body<3>(bid, out, smem);
    else if (bid < 400) deform_body<5>(bid - 200, out, smem);
    else                deform_body<7>(bid - 400, out, smem);
}

// ---------------- launch ----------------
extern "C" void kernel_launch(void* const* d_in, const int* in_sizes, int n_in,
                              void* d_out, int out_size) {
    (void)in_sizes; (void)n_in; (void)out_size;
    const float* x       = (const float*)d_in[0];
    const float* w_off3  = (const float*)d_in[1];
    const float* b_off3  = (const float*)d_in[2];
    const float* w_mask3 = (const float*)d_in[3];
    const float* b_mask3 = (const float*)d_in[4];
    const float* w_dcn3  = (const float*)d_in[5];
    const float* w_off5  = (const float*)d_in[6];
    const float* b_off5  = (const float*)d_in[7];
    const float* w_mask5 = (const float*)d_in[8];
    const float* b_mask5 = (const float*)d_in[9];
    const float* w_dcn5  = (const float*)d_in[10];
    const float* w_off7  = (const float*)d_in[11];
    const float* b_off7  = (const float*)d_in[12];
    const float* w_mask7 = (const float*)d_in[13];
    const float* b_mask7 = (const float*)d_in[14];
    const float* w_dcn7  = (const float*)d_in[15];
    float* out = (float*)d_out;

    k_transpose<<<(BN * HWSZ * CIN + 255) / 256, 256>>>(x);

    k_reorder_conv<3><<<(9  * 27  * CIN + 255) / 256, 256>>>(w_off3, b_off3, w_mask3, b_mask3);
    k_reorder_conv<5><<<(25 * 75  * CIN + 255) / 256, 256>>>(w_off5, b_off5, w_mask5, b_mask5);
    k_reorder_conv<7><<<(49 * 147 * CIN + 255) / 256, 256>>>(w_off7, b_off7, w_mask7, b_mask7);
    k_reorder_dcn<3><<<(9  * COUT * CIN + 255) / 256, 256>>>(w_dcn3);
    k_reorder_dcn<5><<<(25 * COUT * CIN + 255) / 256, 256>>>(w_dcn5);
    k_reorder_dcn<7><<<(49 * COUT * CIN + 255) / 256, 256>>>(w_dcn7);

    k_conv_all<<<600, 256>>>();
    k_deform_all<<<600, 128>>>(out);
}